// round 1
// baseline (speedup 1.0000x reference)
#include <cuda_runtime.h>
#include <cuda_bf16.h>

// Problem constants (fixed by the dataset; runtime sizes derived from in_sizes
// must not exceed these).
#define NMAX 50000
#define CAP  128          // max in-degree bucket capacity (Poisson mean 25)
#define DH   64
#define BGR  512

// ---------------- scratch (static device memory; no allocations) -----------
__device__ int   g_cnt [NMAX];                    // in-degree (excl. self loop)
__device__ float g_dinv[NMAX];                    // rsqrt(deg+1)
__device__ int   g_csr [(size_t)NMAX * CAP];      // bucketed incoming src lists
__device__ float g_h1  [(size_t)NMAX * DH];       // layer outputs (ping)
__device__ float g_h2  [(size_t)NMAX * DH];       // layer outputs (pong)
__device__ float g_g   [(size_t)NMAX * DH];       // dinv-scaled GEMM output
__device__ float g_pool[BGR * DH];                // per-graph feature sums
__device__ int   g_pcnt[BGR];                     // per-graph node counts

// ---------------- setup kernels --------------------------------------------
__global__ void zero_kernel(int n) {
    int i = blockIdx.x * blockDim.x + threadIdx.x;
    if (i < n)        g_cnt[i]  = 0;
    if (i < BGR * DH) g_pool[i] = 0.0f;
    if (i < BGR)      g_pcnt[i] = 0;
}

__global__ void csr_build_kernel(const int* __restrict__ ei, int e_count) {
    int e = blockIdx.x * blockDim.x + threadIdx.x;
    if (e >= e_count) return;
    int src = ei[e];
    int dst = ei[e_count + e];
    int slot = atomicAdd(&g_cnt[dst], 1);
    if (slot < CAP) g_csr[(size_t)dst * CAP + slot] = src;
}

__global__ void node_prep_kernel(const int* __restrict__ batch, int n) {
    int i = blockIdx.x * blockDim.x + threadIdx.x;
    if (i >= n) return;
    g_dinv[i] = rsqrtf((float)g_cnt[i] + 1.0f);   // +1 for self loop
    atomicAdd(&g_pcnt[batch[i]], 1);
}

// ---------------- GEMM: g[r][c] = dinv[r] * sum_k hin[r][k] * W[c][k] -------
// Block: 256 threads = 8 warps; block handles 64 rows. Warp: 8 rows x 64 cols,
// lane owns 2 columns (float2 accumulators). W held transposed in shared.
__global__ __launch_bounds__(256) void gemm_scale_kernel(
    const float* __restrict__ x_ext,   // external input (layer 1)
    int which,                         // 0 -> x_ext, 1 -> g_h1, 2 -> g_h2
    const float* __restrict__ W,       // [64][64] row-major (W[c][k])
    int n)
{
    const float* hin = (which == 0) ? x_ext : (which == 1) ? g_h1 : g_h2;

    __shared__ float Ws[64 * 66];      // Ws[k*66 + c] = W[c][k]  (padded)
    __shared__ float Hs[64 * 64];      // 64 rows of hin

    int tid = threadIdx.x;
    for (int idx = tid; idx < 4096; idx += 256) {
        int c = idx >> 6, k = idx & 63;
        Ws[k * 66 + c] = W[idx];
    }
    int row0 = blockIdx.x * 64;
    for (int idx = tid; idx < 4096; idx += 256) {
        int r = row0 + (idx >> 6);
        Hs[idx] = (r < n) ? hin[(size_t)r * 64 + (idx & 63)] : 0.0f;
    }
    __syncthreads();

    int warp = tid >> 5, lane = tid & 31;
    int r0 = warp * 8;
    int c0 = lane * 2;

    float2 acc[8];
#pragma unroll
    for (int j = 0; j < 8; j++) acc[j] = make_float2(0.f, 0.f);

#pragma unroll 8
    for (int k = 0; k < 64; k++) {
        float2 wv = *(const float2*)&Ws[k * 66 + c0];
#pragma unroll
        for (int j = 0; j < 8; j++) {
            float hv = Hs[(r0 + j) * 64 + k];
            acc[j].x = fmaf(hv, wv.x, acc[j].x);
            acc[j].y = fmaf(hv, wv.y, acc[j].y);
        }
    }

#pragma unroll
    for (int j = 0; j < 8; j++) {
        int r = row0 + r0 + j;
        if (r < n) {
            float dv = g_dinv[r];
            float2 o = make_float2(acc[j].x * dv, acc[j].y * dv);
            *(float2*)&g_g[(size_t)r * 64 + c0] = o;
        }
    }
}

// ---------------- aggregation: one warp per destination node ----------------
// acc = g[i] (self loop) + sum over incoming srcs of g[src]
// out = relu(dinv[i]*acc + bias); mode 1/2 -> write h1/h2, mode 3 -> pool add
__global__ __launch_bounds__(256) void agg_kernel(
    const float* __restrict__ bias,
    const int*   __restrict__ batch,
    int mode, int n)
{
    int w = (blockIdx.x * blockDim.x + threadIdx.x) >> 5;
    if (w >= n) return;
    int lane = threadIdx.x & 31;
    int c0 = lane * 2;

    float2 acc = *(const float2*)&g_g[(size_t)w * 64 + c0];  // self loop

    int cnum = min(g_cnt[w], CAP);
    const int* lst = &g_csr[(size_t)w * CAP];

    int e = 0;
    for (; e + 4 <= cnum; e += 4) {
        int4 s4 = *(const int4*)&lst[e];                     // uniform broadcast
        float2 v0 = *(const float2*)&g_g[(size_t)s4.x * 64 + c0];
        float2 v1 = *(const float2*)&g_g[(size_t)s4.y * 64 + c0];
        float2 v2 = *(const float2*)&g_g[(size_t)s4.z * 64 + c0];
        float2 v3 = *(const float2*)&g_g[(size_t)s4.w * 64 + c0];
        acc.x += (v0.x + v1.x) + (v2.x + v3.x);
        acc.y += (v0.y + v1.y) + (v2.y + v3.y);
    }
    for (; e < cnum; e++) {
        int s = lst[e];
        float2 v = *(const float2*)&g_g[(size_t)s * 64 + c0];
        acc.x += v.x;
        acc.y += v.y;
    }

    float dv = g_dinv[w];
    float2 o;
    o.x = fmaxf(fmaf(dv, acc.x, bias[c0    ]), 0.0f);
    o.y = fmaxf(fmaf(dv, acc.y, bias[c0 + 1]), 0.0f);

    if (mode == 1) {
        *(float2*)&g_h1[(size_t)w * 64 + c0] = o;
    } else if (mode == 2) {
        *(float2*)&g_h2[(size_t)w * 64 + c0] = o;
    } else {
        int b = batch[w];
        atomicAdd(&g_pool[b * 64 + c0    ], o.x);
        atomicAdd(&g_pool[b * 64 + c0 + 1], o.y);
    }
}

// ---------------- final: out[b][o] = mean-pool(b) . Wl[o] + bl[o] -----------
__global__ void final_kernel(const float* __restrict__ Wl,
                             const float* __restrict__ bl,
                             float* __restrict__ out)
{
    int t = blockIdx.x * blockDim.x + threadIdx.x;
    if (t >= BGR * 16) return;
    int b = t >> 4, o = t & 15;
    float inv = 1.0f / fmaxf((float)g_pcnt[b], 1.0f);
    const float* pr = &g_pool[b * 64];
    const float* wr = &Wl[o * 64];
    float s = 0.0f;
#pragma unroll
    for (int k = 0; k < 64; k++) s = fmaf(pr[k], wr[k], s);
    out[t] = fmaf(s, inv, bl[o]);
}

// ---------------- launch ----------------------------------------------------
extern "C" void kernel_launch(void* const* d_in, const int* in_sizes, int n_in,
                              void* d_out, int out_size)
{
    const float* x     = (const float*)d_in[0];
    const int*   ei    = (const int*)  d_in[1];
    const int*   batch = (const int*)  d_in[2];
    const float* W1    = (const float*)d_in[3];
    const float* b1    = (const float*)d_in[4];
    const float* W2    = (const float*)d_in[5];
    const float* b2    = (const float*)d_in[6];
    const float* W3    = (const float*)d_in[7];
    const float* b3    = (const float*)d_in[8];
    const float* Wl    = (const float*)d_in[9];
    const float* bl    = (const float*)d_in[10];
    float* out = (float*)d_out;

    int n = in_sizes[0] / 64;   // 50000
    int e = in_sizes[1] / 2;    // 1250000

    int nb_n = (n + 255) / 256;
    int nb_e = (e + 255) / 256;
    int nb_g = (n + 63) / 64;              // gemm: 64 rows / block
    int nb_a = (n * 32 + 255) / 256;       // agg: 1 warp / node, 8 warps / block

    zero_kernel<<<nb_n, 256>>>(n);
    csr_build_kernel<<<nb_e, 256>>>(ei, e);
    node_prep_kernel<<<nb_n, 256>>>(batch, n);

    gemm_scale_kernel<<<nb_g, 256>>>(x, 0, W1, n);
    agg_kernel<<<nb_a, 256>>>(b1, batch, 1, n);

    gemm_scale_kernel<<<nb_g, 256>>>(x, 1, W2, n);
    agg_kernel<<<nb_a, 256>>>(b2, batch, 2, n);

    gemm_scale_kernel<<<nb_g, 256>>>(x, 2, W3, n);
    agg_kernel<<<nb_a, 256>>>(b3, batch, 3, n);

    final_kernel<<<(BGR * 16 + 255) / 256, 256>>>(Wl, bl, out);
}

// round 2
// speedup vs baseline: 1.2181x; 1.2181x over previous
#include <cuda_runtime.h>
#include <cuda_bf16.h>
#include <cuda_fp16.h>

// Problem constants (fixed by the dataset).
#define NMAX 50000
#define CAP  128          // max in-degree bucket capacity (Poisson mean 25)
#define DH   64
#define BGR  512
#define PAD  68           // padded row stride for shared tiles (floats)

// ---------------- scratch (static device memory; no allocations) -----------
__device__ int     g_cnt [NMAX];                  // in-degree (excl. self loop)
__device__ float   g_dinv[NMAX];                  // rsqrt(deg+1)
__device__ int     g_csr [(size_t)NMAX * CAP];    // bucketed incoming src lists
__device__ float   g_h1  [(size_t)NMAX * DH];     // layer outputs (ping)
__device__ float   g_h2  [(size_t)NMAX * DH];     // layer outputs (pong)
__device__ __half2 g_g   [(size_t)NMAX * 32];     // dinv-scaled GEMM output (fp16)
__device__ float   g_pool[BGR * DH];              // per-graph feature sums
__device__ int     g_pcnt[BGR];                   // per-graph node counts

// ---------------- setup kernels --------------------------------------------
__global__ void zero_kernel(int n) {
    int i = blockIdx.x * blockDim.x + threadIdx.x;
    if (i < n)        g_cnt[i]  = 0;
    if (i < BGR * DH) g_pool[i] = 0.0f;
    if (i < BGR)      g_pcnt[i] = 0;
}

__global__ void csr_build_kernel(const int* __restrict__ ei, int e_count) {
    int e = blockIdx.x * blockDim.x + threadIdx.x;
    if (e >= e_count) return;
    int src = ei[e];
    int dst = ei[e_count + e];
    int slot = atomicAdd(&g_cnt[dst], 1);
    if (slot < CAP) g_csr[(size_t)dst * CAP + slot] = src;
}

__global__ void node_prep_kernel(const int* __restrict__ batch, int n) {
    int i = blockIdx.x * blockDim.x + threadIdx.x;
    if (i >= n) return;
    g_dinv[i] = rsqrtf((float)g_cnt[i] + 1.0f);   // +1 for self loop
    atomicAdd(&g_pcnt[batch[i]], 1);
}

// ---------------- GEMM: g[r][c] = fp16( dinv[r] * sum_k hin[r][k]*W[c][k] ) -
// Block: 256 threads, 64 rows. Thread: 4 rows x 4 cols, k unrolled x4 with
// float4 LDS only (8 LDS.128 per 64 FFMA).
__global__ __launch_bounds__(256) void gemm_scale_kernel(
    const float* __restrict__ x_ext,   // external input (layer 1)
    int which,                         // 0 -> x_ext, 1 -> g_h1, 2 -> g_h2
    const float* __restrict__ W,       // [64][64] row-major (W[c][k])
    int n)
{
    const float* hin = (which == 0) ? x_ext : (which == 1) ? g_h1 : g_h2;

    __shared__ float Ws[64 * PAD];     // Ws[k*PAD + c] = W[c][k]
    __shared__ float Hs[64 * PAD];     // Hs[r*PAD + k] = hin[row0+r][k]

    int tid  = threadIdx.x;
    int row0 = blockIdx.x * 64;

    for (int idx = tid; idx < 4096; idx += 256) {
        int c = idx >> 6, k = idx & 63;
        Ws[k * PAD + c] = W[idx];
    }
    for (int i = tid; i < 1024; i += 256) {       // 1024 float4 tiles
        int r = i >> 4, c4 = (i & 15) << 2;
        float4 v = make_float4(0.f, 0.f, 0.f, 0.f);
        if (row0 + r < n)
            v = *(const float4*)&hin[(size_t)(row0 + r) * 64 + c4];
        *(float4*)&Hs[r * PAD + c4] = v;
    }
    __syncthreads();

    int c0 = (tid & 15) << 2;          // 4 cols
    int r0 = (tid >> 4) << 2;          // 4 rows

    float4 acc0 = make_float4(0.f,0.f,0.f,0.f);
    float4 acc1 = acc0, acc2 = acc0, acc3 = acc0;

#pragma unroll 4
    for (int kk = 0; kk < 64; kk += 4) {
        float4 h0 = *(const float4*)&Hs[(r0 + 0) * PAD + kk];
        float4 h1 = *(const float4*)&Hs[(r0 + 1) * PAD + kk];
        float4 h2 = *(const float4*)&Hs[(r0 + 2) * PAD + kk];
        float4 h3 = *(const float4*)&Hs[(r0 + 3) * PAD + kk];
        float4 w0 = *(const float4*)&Ws[(kk + 0) * PAD + c0];
        float4 w1 = *(const float4*)&Ws[(kk + 1) * PAD + c0];
        float4 w2 = *(const float4*)&Ws[(kk + 2) * PAD + c0];
        float4 w3 = *(const float4*)&Ws[(kk + 3) * PAD + c0];

#define STEP(ACC, H)                                               \
        ACC.x = fmaf(H.x, w0.x, ACC.x); ACC.y = fmaf(H.x, w0.y, ACC.y); \
        ACC.z = fmaf(H.x, w0.z, ACC.z); ACC.w = fmaf(H.x, w0.w, ACC.w); \
        ACC.x = fmaf(H.y, w1.x, ACC.x); ACC.y = fmaf(H.y, w1.y, ACC.y); \
        ACC.z = fmaf(H.y, w1.z, ACC.z); ACC.w = fmaf(H.y, w1.w, ACC.w); \
        ACC.x = fmaf(H.z, w2.x, ACC.x); ACC.y = fmaf(H.z, w2.y, ACC.y); \
        ACC.z = fmaf(H.z, w2.z, ACC.z); ACC.w = fmaf(H.z, w2.w, ACC.w); \
        ACC.x = fmaf(H.w, w3.x, ACC.x); ACC.y = fmaf(H.w, w3.y, ACC.y); \
        ACC.z = fmaf(H.w, w3.z, ACC.z); ACC.w = fmaf(H.w, w3.w, ACC.w);
        STEP(acc0, h0) STEP(acc1, h1) STEP(acc2, h2) STEP(acc3, h3)
#undef STEP
    }

    float4 accs[4] = {acc0, acc1, acc2, acc3};
#pragma unroll
    for (int j = 0; j < 4; j++) {
        int r = row0 + r0 + j;
        if (r < n) {
            float dv = g_dinv[r];
            __half2 p[2];
            p[0] = __floats2half2_rn(accs[j].x * dv, accs[j].y * dv);
            p[1] = __floats2half2_rn(accs[j].z * dv, accs[j].w * dv);
            *(uint2*)&g_g[(size_t)r * 32 + (c0 >> 1)] = *(uint2*)p;
        }
    }
}

// ---------------- aggregation: one warp per destination node ----------------
// acc = g[i] (self loop) + sum over incoming srcs of g[src]   (g is fp16)
// out = relu(dinv[i]*acc + bias); mode 1/2 -> write h1/h2, mode 3 -> pool add
__global__ __launch_bounds__(256) void agg_kernel(
    const float* __restrict__ bias,
    const int*   __restrict__ batch,
    int mode, int n)
{
    int w = (blockIdx.x * blockDim.x + threadIdx.x) >> 5;
    if (w >= n) return;
    int lane = threadIdx.x & 31;
    int c0 = lane * 2;

    float2 acc = __half22float2(g_g[(size_t)w * 32 + lane]);  // self loop

    int cnum = min(g_cnt[w], CAP);
    const int* lst = &g_csr[(size_t)w * CAP];

    int e = 0;
    for (; e + 4 <= cnum; e += 4) {
        int4 s4 = *(const int4*)&lst[e];                      // uniform broadcast
        float2 v0 = __half22float2(g_g[(size_t)s4.x * 32 + lane]);
        float2 v1 = __half22float2(g_g[(size_t)s4.y * 32 + lane]);
        float2 v2 = __half22float2(g_g[(size_t)s4.z * 32 + lane]);
        float2 v3 = __half22float2(g_g[(size_t)s4.w * 32 + lane]);
        acc.x += (v0.x + v1.x) + (v2.x + v3.x);
        acc.y += (v0.y + v1.y) + (v2.y + v3.y);
    }
    for (; e < cnum; e++) {
        int s = lst[e];
        float2 v = __half22float2(g_g[(size_t)s * 32 + lane]);
        acc.x += v.x;
        acc.y += v.y;
    }

    float dv = g_dinv[w];
    float2 o;
    o.x = fmaxf(fmaf(dv, acc.x, bias[c0    ]), 0.0f);
    o.y = fmaxf(fmaf(dv, acc.y, bias[c0 + 1]), 0.0f);

    if (mode == 1) {
        *(float2*)&g_h1[(size_t)w * 64 + c0] = o;
    } else if (mode == 2) {
        *(float2*)&g_h2[(size_t)w * 64 + c0] = o;
    } else {
        int b = batch[w];
        atomicAdd(&g_pool[b * 64 + c0    ], o.x);
        atomicAdd(&g_pool[b * 64 + c0 + 1], o.y);
    }
}

// ---------------- final: out[b][o] = mean-pool(b) . Wl[o] + bl[o] -----------
__global__ void final_kernel(const float* __restrict__ Wl,
                             const float* __restrict__ bl,
                             float* __restrict__ out)
{
    int t = blockIdx.x * blockDim.x + threadIdx.x;
    if (t >= BGR * 16) return;
    int b = t >> 4, o = t & 15;
    float inv = 1.0f / fmaxf((float)g_pcnt[b], 1.0f);
    const float* pr = &g_pool[b * 64];
    const float* wr = &Wl[o * 64];
    float s = 0.0f;
#pragma unroll
    for (int k = 0; k < 64; k++) s = fmaf(pr[k], wr[k], s);
    out[t] = fmaf(s, inv, bl[o]);
}

// ---------------- launch ----------------------------------------------------
extern "C" void kernel_launch(void* const* d_in, const int* in_sizes, int n_in,
                              void* d_out, int out_size)
{
    const float* x     = (const float*)d_in[0];
    const int*   ei    = (const int*)  d_in[1];
    const int*   batch = (const int*)  d_in[2];
    const float* W1    = (const float*)d_in[3];
    const float* b1    = (const float*)d_in[4];
    const float* W2    = (const float*)d_in[5];
    const float* b2    = (const float*)d_in[6];
    const float* W3    = (const float*)d_in[7];
    const float* b3    = (const float*)d_in[8];
    const float* Wl    = (const float*)d_in[9];
    const float* bl    = (const float*)d_in[10];
    float* out = (float*)d_out;

    int n = in_sizes[0] / 64;   // 50000
    int e = in_sizes[1] / 2;    // 1250000

    int nb_n = (n + 255) / 256;
    int nb_e = (e + 255) / 256;
    int nb_g = (n + 63) / 64;              // gemm: 64 rows / block
    int nb_a = (n * 32 + 255) / 256;       // agg: 1 warp / node

    zero_kernel<<<nb_n, 256>>>(n);
    csr_build_kernel<<<nb_e, 256>>>(ei, e);
    node_prep_kernel<<<nb_n, 256>>>(batch, n);

    gemm_scale_kernel<<<nb_g, 256>>>(x, 0, W1, n);
    agg_kernel<<<nb_a, 256>>>(b1, batch, 1, n);

    gemm_scale_kernel<<<nb_g, 256>>>(x, 1, W2, n);
    agg_kernel<<<nb_a, 256>>>(b2, batch, 2, n);

    gemm_scale_kernel<<<nb_g, 256>>>(x, 2, W3, n);
    agg_kernel<<<nb_a, 256>>>(b3, batch, 3, n);

    final_kernel<<<(BGR * 16 + 255) / 256, 256>>>(Wl, bl, out);
}

// round 3
// speedup vs baseline: 1.3359x; 1.0967x over previous
#include <cuda_runtime.h>
#include <cuda_bf16.h>
#include <cuda_fp16.h>

// Problem constants (fixed by the dataset).
#define NMAX 50000
#define CAP  128          // max in-degree bucket capacity (Poisson mean 25)
#define DH   64
#define BGR  512

// ---------------- scratch (static device memory; no allocations) -----------
__device__ int     g_cnt [NMAX];                  // in-degree (excl. self loop)
__device__ float   g_dinv[NMAX];                  // rsqrt(deg+1)
__device__ int     g_csr [(size_t)NMAX * CAP];    // bucketed incoming src lists
__device__ __half2 g_hx  [(size_t)NMAX * 32];     // x converted to fp16
__device__ __half2 g_h1  [(size_t)NMAX * 32];     // layer outputs (ping, fp16)
__device__ __half2 g_h2  [(size_t)NMAX * 32];     // layer outputs (pong, fp16)
__device__ __half2 g_g   [(size_t)NMAX * 32];     // dinv-scaled GEMM output
__device__ float   g_pool[BGR * DH];              // per-graph feature sums
__device__ int     g_pcnt[BGR];                   // per-graph node counts

// ---------------- setup kernels --------------------------------------------
__global__ void zero_kernel(int n) {
    int i = blockIdx.x * blockDim.x + threadIdx.x;
    if (i < n)        g_cnt[i]  = 0;
    if (i < BGR * DH) g_pool[i] = 0.0f;
    if (i < BGR)      g_pcnt[i] = 0;
}

__global__ void csr_build_kernel(const int* __restrict__ ei, int e_count) {
    int e = blockIdx.x * blockDim.x + threadIdx.x;
    if (e >= e_count) return;
    int src = ei[e];
    int dst = ei[e_count + e];
    int slot = atomicAdd(&g_cnt[dst], 1);
    if (slot < CAP) g_csr[(size_t)dst * CAP + slot] = src;
}

__global__ void node_prep_kernel(const int* __restrict__ batch, int n) {
    int i = blockIdx.x * blockDim.x + threadIdx.x;
    if (i >= n) return;
    g_dinv[i] = rsqrtf((float)g_cnt[i] + 1.0f);   // +1 for self loop
    atomicAdd(&g_pcnt[batch[i]], 1);
}

// x (fp32) -> g_hx (fp16)
__global__ void cvt_x_kernel(const float* __restrict__ x, int nh2) {
    int i = blockIdx.x * blockDim.x + threadIdx.x;
    if (i >= nh2) return;
    float2 v = ((const float2*)x)[i];
    ((__half2*)g_hx)[i] = __floats2half2_rn(v.x, v.y);
}

// ---------------- GEMM via mma.sync.m16n8k16 (fp16 in, fp32 acc) -----------
// out[r][c] = dinv[r] * sum_k hin[r][k] * W[c][k], written fp16 to g_g.
// Each warp: W resident in 64 half2 B-registers; loops over 16-row tiles.
// Fragment mapping (g = lane>>2, t = lane&3):
//   A: a0=(row g, k 2t..), a1=(g+8, 2t..), a2=(g, 2t+8..), a3=(g+8, 2t+8..)
//   B: b0=(k 2t.., n g),   b1=(k 2t+8.., n g)   [= W[n][k] row-major pairs]
//   C: c0=(g,2t) c1=(g,2t+1) c2=(g+8,2t) c3=(g+8,2t+1)
__global__ __launch_bounds__(256, 1) void gemm_mma_kernel(
    int which, const float* __restrict__ W, int n)
{
    const __half2* hin = (which == 0) ? g_hx : (which == 1) ? g_h1 : g_h2;

    int lane = threadIdx.x & 31;
    int g = lane >> 2, t = lane & 3;

    // Load + convert W into resident B fragments (broadcast; L1 served).
    unsigned b[4][8][2];
#pragma unroll
    for (int kc = 0; kc < 4; kc++)
#pragma unroll
        for (int nt = 0; nt < 8; nt++) {
            const float* wr = &W[(nt * 8 + g) * 64 + kc * 16 + 2 * t];
            float2 x0 = *(const float2*)(wr);
            float2 x1 = *(const float2*)(wr + 8);
            __half2 h0 = __floats2half2_rn(x0.x, x0.y);
            __half2 h1 = __floats2half2_rn(x1.x, x1.y);
            b[kc][nt][0] = *(unsigned*)&h0;
            b[kc][nt][1] = *(unsigned*)&h1;
        }

    int warp_id = (blockIdx.x * blockDim.x + threadIdx.x) >> 5;
    int nwarps  = (gridDim.x * blockDim.x) >> 5;
    int ntiles  = (n + 15) >> 4;

    for (int rt = warp_id; rt < ntiles; rt += nwarps) {
        int row0 = rt * 16;
        int r_lo = row0 + g;
        int r_hi = row0 + g + 8;
        bool full = (row0 + 16 <= n);

        const __half2* plo = hin + (size_t)r_lo * 32;
        const __half2* phi = hin + (size_t)r_hi * 32;

        unsigned a[4][4];
#pragma unroll
        for (int kc = 0; kc < 4; kc++) {
            if (full || r_lo < n) {
                a[kc][0] = *(const unsigned*)&plo[kc * 8 + t];
                a[kc][2] = *(const unsigned*)&plo[kc * 8 + t + 4];
            } else { a[kc][0] = 0u; a[kc][2] = 0u; }
            if (full || r_hi < n) {
                a[kc][1] = *(const unsigned*)&phi[kc * 8 + t];
                a[kc][3] = *(const unsigned*)&phi[kc * 8 + t + 4];
            } else { a[kc][1] = 0u; a[kc][3] = 0u; }
        }

        float c[8][4];
#pragma unroll
        for (int nt = 0; nt < 8; nt++) { c[nt][0]=0.f; c[nt][1]=0.f; c[nt][2]=0.f; c[nt][3]=0.f; }

#pragma unroll
        for (int kc = 0; kc < 4; kc++)
#pragma unroll
            for (int nt = 0; nt < 8; nt++) {
                asm volatile(
                    "mma.sync.aligned.m16n8k16.row.col.f32.f16.f16.f32 "
                    "{%0,%1,%2,%3}, {%4,%5,%6,%7}, {%8,%9}, {%0,%1,%2,%3};"
                    : "+f"(c[nt][0]), "+f"(c[nt][1]), "+f"(c[nt][2]), "+f"(c[nt][3])
                    : "r"(a[kc][0]), "r"(a[kc][1]), "r"(a[kc][2]), "r"(a[kc][3]),
                      "r"(b[kc][nt][0]), "r"(b[kc][nt][1]));
            }

        // epilogue: scale by dinv, pack fp16, store
        if (full || r_lo < n) {
            float dlo = g_dinv[r_lo];
            __half2* olo = g_g + (size_t)r_lo * 32;
#pragma unroll
            for (int nt = 0; nt < 8; nt++)
                olo[nt * 4 + t] = __floats2half2_rn(c[nt][0] * dlo, c[nt][1] * dlo);
        }
        if (full || r_hi < n) {
            float dhi = g_dinv[r_hi];
            __half2* ohi = g_g + (size_t)r_hi * 32;
#pragma unroll
            for (int nt = 0; nt < 8; nt++)
                ohi[nt * 4 + t] = __floats2half2_rn(c[nt][2] * dhi, c[nt][3] * dhi);
        }
    }
}

// ---------------- aggregation: one warp per destination node ----------------
// acc = g[i] (self loop) + sum over incoming srcs of g[src]   (g is fp16)
// out = relu(dinv[i]*acc + bias); mode 1/2 -> write h1/h2 (fp16), 3 -> pool
__global__ __launch_bounds__(256) void agg_kernel(
    const float* __restrict__ bias,
    const int*   __restrict__ batch,
    int mode, int n)
{
    int w = (blockIdx.x * blockDim.x + threadIdx.x) >> 5;
    if (w >= n) return;
    int lane = threadIdx.x & 31;
    int c0 = lane * 2;

    float2 acc = __half22float2(g_g[(size_t)w * 32 + lane]);  // self loop

    int cnum = min(g_cnt[w], CAP);
    const int* lst = &g_csr[(size_t)w * CAP];

    int e = 0;
    for (; e + 4 <= cnum; e += 4) {
        int4 s4 = *(const int4*)&lst[e];                      // uniform broadcast
        float2 v0 = __half22float2(g_g[(size_t)s4.x * 32 + lane]);
        float2 v1 = __half22float2(g_g[(size_t)s4.y * 32 + lane]);
        float2 v2 = __half22float2(g_g[(size_t)s4.z * 32 + lane]);
        float2 v3 = __half22float2(g_g[(size_t)s4.w * 32 + lane]);
        acc.x += (v0.x + v1.x) + (v2.x + v3.x);
        acc.y += (v0.y + v1.y) + (v2.y + v3.y);
    }
    for (; e < cnum; e++) {
        int s = lst[e];
        float2 v = __half22float2(g_g[(size_t)s * 32 + lane]);
        acc.x += v.x;
        acc.y += v.y;
    }

    float dv = g_dinv[w];
    float ox = fmaxf(fmaf(dv, acc.x, bias[c0    ]), 0.0f);
    float oy = fmaxf(fmaf(dv, acc.y, bias[c0 + 1]), 0.0f);

    if (mode == 1) {
        g_h1[(size_t)w * 32 + lane] = __floats2half2_rn(ox, oy);
    } else if (mode == 2) {
        g_h2[(size_t)w * 32 + lane] = __floats2half2_rn(ox, oy);
    } else {
        int b = batch[w];
        atomicAdd(&g_pool[b * 64 + c0    ], ox);
        atomicAdd(&g_pool[b * 64 + c0 + 1], oy);
    }
}

// ---------------- final: out[b][o] = mean-pool(b) . Wl[o] + bl[o] -----------
__global__ void final_kernel(const float* __restrict__ Wl,
                             const float* __restrict__ bl,
                             float* __restrict__ out)
{
    int t = blockIdx.x * blockDim.x + threadIdx.x;
    if (t >= BGR * 16) return;
    int b = t >> 4, o = t & 15;
    float inv = 1.0f / fmaxf((float)g_pcnt[b], 1.0f);
    const float* pr = &g_pool[b * 64];
    const float* wr = &Wl[o * 64];
    float s = 0.0f;
#pragma unroll
    for (int k = 0; k < 64; k++) s = fmaf(pr[k], wr[k], s);
    out[t] = fmaf(s, inv, bl[o]);
}

// ---------------- launch ----------------------------------------------------
extern "C" void kernel_launch(void* const* d_in, const int* in_sizes, int n_in,
                              void* d_out, int out_size)
{
    const float* x     = (const float*)d_in[0];
    const int*   ei    = (const int*)  d_in[1];
    const int*   batch = (const int*)  d_in[2];
    const float* W1    = (const float*)d_in[3];
    const float* b1    = (const float*)d_in[4];
    const float* W2    = (const float*)d_in[5];
    const float* b2    = (const float*)d_in[6];
    const float* W3    = (const float*)d_in[7];
    const float* b3    = (const float*)d_in[8];
    const float* Wl    = (const float*)d_in[9];
    const float* bl    = (const float*)d_in[10];
    float* out = (float*)d_out;

    int n = in_sizes[0] / 64;   // 50000
    int e = in_sizes[1] / 2;    // 1250000

    int nb_n = (n + 255) / 256;
    int nb_e = (e + 255) / 256;
    int nb_c = (n * 32 + 255) / 256;       // cvt: n*32 half2 elems
    int nb_a = (n * 32 + 255) / 256;       // agg: 1 warp / node
    int nb_m = 196;                        // gemm: 1568 warps ~ 2 tiles/warp

    zero_kernel<<<nb_n, 256>>>(n);
    csr_build_kernel<<<nb_e, 256>>>(ei, e);
    node_prep_kernel<<<nb_n, 256>>>(batch, n);
    cvt_x_kernel<<<nb_c, 256>>>(x, n * 32);

    gemm_mma_kernel<<<nb_m, 256>>>(0, W1, n);
    agg_kernel<<<nb_a, 256>>>(b1, batch, 1, n);

    gemm_mma_kernel<<<nb_m, 256>>>(1, W2, n);
    agg_kernel<<<nb_a, 256>>>(b2, batch, 2, n);

    gemm_mma_kernel<<<nb_m, 256>>>(2, W3, n);
    agg_kernel<<<nb_a, 256>>>(b3, batch, 3, n);

    final_kernel<<<(BGR * 16 + 255) / 256, 256>>>(Wl, bl, out);
}